// round 11
// baseline (speedup 1.0000x reference)
#include <cuda_runtime.h>

// LengthRegulator, fused single kernel, zero block barriers:
// every warp independently scans the batch's 512 durations (16/lane serial +
// shfl exclusive prefix) and scatters this block's 64-frame frame->token map
// into a warp-private smem window. Only __syncwarp() needed. The 12 warps'
// prologues overlap other warps'/blocks' copy phases instead of blocking them.

#define BB 32
#define SS 512
#define DD 384
#define T_OUT 2048
#define DV (DD / 4)     // 96 float4 per row
#define FRB 64          // frames per block
#define NT 384          // threads per block (12 warps, all SMSPs)
#define FL 4            // frame lanes (NT / DV)
#define NW (NT / 32)    // 12 warps

__global__ __launch_bounds__(NT)
void lr_fused_kernel(const float4* __restrict__ x4,
                     const int* __restrict__ dur,
                     float4* __restrict__ out4) {
    __shared__ int sidx[NW][FRB];      // warp-private frame->token windows

    const int b    = blockIdx.y;
    const int t0   = blockIdx.x * FRB;
    const int tid  = threadIdx.x;
    const int w    = tid >> 5;
    const int lane = tid & 31;

    // ── per-warp prologue (no cross-warp sync) ──────────────────────────
    {
        // lane owns tokens [lane*16, lane*16+16): 4 independent int4 loads
        // (L2-resident after first touch; MLP=4)
        const int4* dp = (const int4*)(dur + b * SS) + lane * 4;
        const int4 q0 = __ldg(&dp[0]);
        const int4 q1 = __ldg(&dp[1]);
        const int4 q2 = __ldg(&dp[2]);
        const int4 q3 = __ldg(&dp[3]);
        const int d[16] = {q0.x, q0.y, q0.z, q0.w, q1.x, q1.y, q1.z, q1.w,
                           q2.x, q2.y, q2.z, q2.w, q3.x, q3.y, q3.z, q3.w};

        int sum = 0;
        #pragma unroll
        for (int i = 0; i < 16; ++i) sum += d[i];

        // exclusive warp prefix of per-lane sums
        int pref = sum;
        #pragma unroll
        for (int off = 1; off < 32; off <<= 1) {
            int v = __shfl_up_sync(0xFFFFFFFFu, pref, off);
            if (lane >= off) pref += v;
        }
        int start = pref - sum;        // exclusive start of this lane's tokens

        // scatter clipped intervals into this warp's private window
        #pragma unroll
        for (int i = 0; i < 16; ++i) {
            const int e = start + d[i];
            int lo = start > t0 ? start : t0;
            int hi = e < t0 + FRB ? e : t0 + FRB;
            for (int k = lo; k < hi; ++k)
                sidx[w][k - t0] = lane * 16 + i;
            start = e;
        }
        __syncwarp();                  // writes visible within the warp only
    }

    // ── copy: c = channel (0..95 float4), f = frame lane (0..3) ─────────
    // f is uniform per warp; all 32 lanes broadcast-read the same sidx entry.
    const int c = tid % DV;            // contiguous within warp
    const int f = tid / DV;
    const float4* __restrict__ xb = x4 + (size_t)b * SS * DV + c;
    float4* __restrict__ ob = out4 + ((size_t)b * T_OUT + t0) * DV + c;

    #pragma unroll
    for (int g = 0; g < FRB / FL; g += 4) {
        int tk[4];
        #pragma unroll
        for (int i = 0; i < 4; ++i)
            tk[i] = sidx[w][f + FL * (g + i)];

        float4 v[4];
        #pragma unroll
        for (int i = 0; i < 4; ++i)
            v[i] = __ldg(&xb[(size_t)tk[i] * DV]);

        #pragma unroll
        for (int i = 0; i < 4; ++i)
            __stcs(&ob[(size_t)(f + FL * (g + i)) * DV], v[i]);
    }
}

extern "C" void kernel_launch(void* const* d_in, const int* in_sizes, int n_in,
                              void* d_out, int out_size) {
    const float4* x4  = (const float4*)d_in[0];   // x [B,S,D] f32
    const int*    dur = (const int*)d_in[1];      // durations [B,S] i32
    float4* out4 = (float4*)d_out;                // [B,T_OUT,D] f32

    lr_fused_kernel<<<dim3(T_OUT / FRB, BB), NT>>>(x4, dur, out4);
}

// round 12
// speedup vs baseline: 1.1688x; 1.1688x over previous
#include <cuda_runtime.h>

// LengthRegulator, two kernels (proven-fastest structure):
//   kernel 1: one warp per batch — shfl exclusive scan of 512 durations,
//             zero barriers, writes g_start (launch-latency-bound, <1us)
//   kernel 2: R2 champion scatter expand (21.1us measured): block (j,b)
//             copies x[b,j,:] into its dur frames with streaming stores.

#define BB 32
#define SS 512
#define DD 384
#define T_OUT 2048
#define DV (DD / 4)   // 96 float4 per row

// Exclusive-cumsum start offsets per (b, token). Device global (no-alloc rule).
__device__ int g_start[BB * SS];

// Kernel 1: warp-per-batch exclusive scan. 32 blocks x 32 threads.
__global__ void lr_scan_kernel(const int* __restrict__ dur) {
    const int b    = blockIdx.x;
    const int lane = threadIdx.x;

    // lane owns tokens [lane*16, lane*16+16): 4 independent int4 loads
    const int4* dp = (const int4*)(dur + b * SS) + lane * 4;
    const int4 q0 = __ldg(&dp[0]);
    const int4 q1 = __ldg(&dp[1]);
    const int4 q2 = __ldg(&dp[2]);
    const int4 q3 = __ldg(&dp[3]);
    const int d[16] = {q0.x, q0.y, q0.z, q0.w, q1.x, q1.y, q1.z, q1.w,
                       q2.x, q2.y, q2.z, q2.w, q3.x, q3.y, q3.z, q3.w};

    int sum = 0;
    #pragma unroll
    for (int i = 0; i < 16; ++i) sum += d[i];

    // exclusive warp prefix of per-lane sums
    int pref = sum;
    #pragma unroll
    for (int off = 1; off < 32; off <<= 1) {
        int v = __shfl_up_sync(0xFFFFFFFFu, pref, off);
        if (lane >= off) pref += v;
    }
    int start = pref - sum;            // exclusive start of this lane's block

    // per-lane exclusive starts, written back as 4 x int4
    int s[16];
    #pragma unroll
    for (int i = 0; i < 16; ++i) { s[i] = start; start += d[i]; }

    int4* gp = (int4*)(g_start + b * SS) + lane * 4;
    gp[0] = make_int4(s[0],  s[1],  s[2],  s[3]);
    gp[1] = make_int4(s[4],  s[5],  s[6],  s[7]);
    gp[2] = make_int4(s[8],  s[9],  s[10], s[11]);
    gp[3] = make_int4(s[12], s[13], s[14], s[15]);
}

// Kernel 2: block (j, b) copies x[b,j,:] into out frames [start, start+dur).
// 96 threads, one float4 each: row read is one coalesced 1536B transaction,
// each frame write is one coalesced 1536B streaming-store transaction.
__global__ void lr_expand_kernel(const float4* __restrict__ x4,
                                 const int* __restrict__ dur,
                                 float4* __restrict__ out4) {
    const int j = blockIdx.x;
    const int b = blockIdx.y;
    const int c = threadIdx.x;           // 0..95
    const int idx = b * SS + j;

    const float4 v = __ldg(&x4[(size_t)idx * DV + c]);
    const int start = g_start[idx];
    const int d = dur[idx];

    float4* o = out4 + ((size_t)b * T_OUT + start) * DV + c;
    for (int k = 0; k < d; ++k) {
        __stcs(&o[(size_t)k * DV], v);   // streaming store: output never re-read
    }
}

extern "C" void kernel_launch(void* const* d_in, const int* in_sizes, int n_in,
                              void* d_out, int out_size) {
    const float4* x4  = (const float4*)d_in[0];   // x [B,S,D] f32
    const int*    dur = (const int*)d_in[1];      // durations [B,S] i32
    float4* out4 = (float4*)d_out;                // [B,T_OUT,D] f32

    lr_scan_kernel<<<BB, 32>>>(dur);
    lr_expand_kernel<<<dim3(SS, BB), DV>>>(x4, dur, out4);
}

// round 13
// speedup vs baseline: 1.2875x; 1.1016x over previous
#include <cuda_runtime.h>

// LengthRegulator, single fused kernel (one graph node):
// block (j,b) computes ONLY its own start offset = sum(dur[b,0..j)) with a
// 96-thread strided partial sum + shfl reduce (one barrier, ~70 instr),
// then runs the champion scatter copy (measured 20.0us as a standalone).

#define BB 32
#define SS 512
#define DD 384
#define T_OUT 2048
#define DV (DD / 4)   // 96 float4 per row

__global__ __launch_bounds__(DV)
void lr_fused_kernel(const float4* __restrict__ x4,
                     const int* __restrict__ dur,
                     float4* __restrict__ out4) {
    __shared__ int part[3];

    const int j = blockIdx.x;
    const int b = blockIdx.y;
    const int t = threadIdx.x;           // 0..95 = float4 channel
    const int w = t >> 5;
    const int lane = t & 31;
    const int idx = b * SS + j;

    // Issue the x-row load first — its DRAM latency overlaps the prologue.
    const float4 v = __ldg(&x4[(size_t)idx * DV + t]);

    // ── prologue: start = sum_{p<j} dur[b,p] ────────────────────────────
    const int* dr = dur + b * SS;
    int sum = 0;
    for (int p = t; p < j; p += DV)      // <= 6 predicated L2-hit loads
        sum += __ldg(&dr[p]);
    #pragma unroll
    for (int off = 16; off > 0; off >>= 1)
        sum += __shfl_down_sync(0xFFFFFFFFu, sum, off);
    if (lane == 0) part[w] = sum;
    __syncthreads();
    const int start = part[0] + part[1] + part[2];
    const int d = __ldg(&dr[j]);         // broadcast, L1/L2 hit

    // ── copy: one float4 lane per thread, streaming stores ──────────────
    float4* o = out4 + ((size_t)b * T_OUT + start) * DV + t;
    for (int k = 0; k < d; ++k)
        __stcs(&o[(size_t)k * DV], v);   // output never re-read
}

extern "C" void kernel_launch(void* const* d_in, const int* in_sizes, int n_in,
                              void* d_out, int out_size) {
    const float4* x4  = (const float4*)d_in[0];   // x [B,S,D] f32
    const int*    dur = (const int*)d_in[1];      // durations [B,S] i32
    float4* out4 = (float4*)d_out;                // [B,T_OUT,D] f32

    lr_fused_kernel<<<dim3(SS, BB), DV>>>(x4, dur, out4);
}